// round 11
// baseline (speedup 1.0000x reference)
#include <cuda_runtime.h>

// ---------------------------------------------------------------------------
// MHSA with (bug-faithful) RPE, fp32, packed-f32x2 FFMA2, pipelined tiles.
//   per (b,h):  L = Q K^T / 14 + C_h Q ; A = softmax(L) ; O = A V
//   out = O Wo^T + bo
// ---------------------------------------------------------------------------

typedef unsigned long long u64;

constexpr int Bn = 256;
constexpr int Tn = 196;
constexpr int Cn = 784;
constexpr int Hn = 4;
constexpr int Dn = 196;
constexpr int HGTn = 14;
constexpr int WIDn = 14;
constexpr int BHn = Bn * Hn;     // 1024
constexpr int SQn = Tn * Dn;     // 38416
constexpr int Rows = Bn * Tn;    // 50176

__device__ float g_q[(size_t)BHn * SQn];
__device__ float g_k[(size_t)BHn * SQn];
__device__ float g_v[(size_t)BHn * SQn];
__device__ float g_l[(size_t)BHn * SQn];
__device__ float g_o[(size_t)Rows * Cn];
__device__ float g_cp[(size_t)Hn * SQn];

static __device__ __forceinline__ float4 f4zero() { return make_float4(0.f, 0.f, 0.f, 0.f); }

static __device__ __forceinline__ u64 dup2(float v) {
    u64 r; asm("mov.b64 %0, {%1,%1};" : "=l"(r) : "f"(v)); return r;
}
static __device__ __forceinline__ void ffma2(u64& d, u64 a, u64 b) {
    asm("fma.rn.f32x2 %0, %1, %2, %3;" : "=l"(d) : "l"(a), "l"(b), "l"(d));
}
static __device__ __forceinline__ float2 unpack2(u64 p) {
    float2 f; asm("mov.b64 {%0,%1}, %2;" : "=f"(f.x), "=f"(f.y) : "l"(p)); return f;
}

// ---------------------------------------------------------------------------
__global__ void build_cp_kernel(const float* __restrict__ rel_h,
                                const float* __restrict__ rel_w)
{
    int idx = blockIdx.x * blockDim.x + threadIdx.x;
    if (idx >= Hn * SQn) return;
    int t = idx % Dn;
    int p = (idx / Dn) % Tn;
    int h = idx / (Dn * Tn);
    g_cp[idx] = rel_h[(h * Dn + t) * HGTn + (p / WIDn)]
              + rel_w[(h * Dn + t) * WIDn + (p % WIDn)];
}

// ---------------------------------------------------------------------------
// NT SGEMM, CTA 128x112 (exact: 7*112=784), BK=16, 256 thr, double-buffered.
// Per-thread 8(m, as 4 pairs) x 7(n). B pre-duplicated as {v,v} u64 pairs.
// OUT_SEL: 0 -> row-major outp (A = g_o); 1/2/3 -> scatter g_q/g_k/g_v.
// ---------------------------------------------------------------------------
template <int OUT_SEL>
__global__ void __launch_bounds__(256, 2) proj_kernel(const float* __restrict__ Ain,
                                                      const float* __restrict__ W,
                                                      const float* __restrict__ bias,
                                                      float* __restrict__ outp)
{
    const float* __restrict__ A = (OUT_SEL == 0) ? g_o : Ain;

    __shared__ __align__(16) float As[2][16][132];   // [buf][k][m]
    __shared__ __align__(16) u64  Bs[2][16][114];    // [buf][k][n] duplicated pairs

    const int tid = threadIdx.x;
    const int m0 = blockIdx.y * 128;
    const int n0 = blockIdx.x * 112;
    const int ty = tid >> 4, tx = tid & 15;
    const int lr = tid >> 2;
    const int lc4 = (tid & 3) * 4;
    const bool wb1v = (lr < 48);

    const float* __restrict__ Ab0 = A + (size_t)(m0 + lr) * Cn + lc4;
    const float* __restrict__ Ab1 = A + (size_t)(m0 + lr + 64) * Cn + lc4;
    const float* __restrict__ Wb0 = W + (size_t)(n0 + lr) * Cn + lc4;
    const float* __restrict__ Wb1 = W + (size_t)(n0 + 64 + lr) * Cn + lc4;

    u64 acc[4][7];
#pragma unroll
    for (int i = 0; i < 4; i++)
#pragma unroll
        for (int j = 0; j < 7; j++) acc[i][j] = 0ull;

    float4 a0, a1, b0, b1;
    auto LDG = [&](int kt) {
        const int k0 = kt * 16;
        a0 = *(const float4*)(Ab0 + k0);
        a1 = *(const float4*)(Ab1 + k0);
        b0 = *(const float4*)(Wb0 + k0);
        b1 = wb1v ? *(const float4*)(Wb1 + k0) : f4zero();
    };
    auto STS = [&](int bf) {
        As[bf][lc4 + 0][lr] = a0.x; As[bf][lc4 + 1][lr] = a0.y;
        As[bf][lc4 + 2][lr] = a0.z; As[bf][lc4 + 3][lr] = a0.w;
        As[bf][lc4 + 0][lr + 64] = a1.x; As[bf][lc4 + 1][lr + 64] = a1.y;
        As[bf][lc4 + 2][lr + 64] = a1.z; As[bf][lc4 + 3][lr + 64] = a1.w;
        Bs[bf][lc4 + 0][lr] = dup2(b0.x); Bs[bf][lc4 + 1][lr] = dup2(b0.y);
        Bs[bf][lc4 + 2][lr] = dup2(b0.z); Bs[bf][lc4 + 3][lr] = dup2(b0.w);
        if (wb1v) {
            Bs[bf][lc4 + 0][64 + lr] = dup2(b1.x); Bs[bf][lc4 + 1][64 + lr] = dup2(b1.y);
            Bs[bf][lc4 + 2][64 + lr] = dup2(b1.z); Bs[bf][lc4 + 3][64 + lr] = dup2(b1.w);
        }
    };

    LDG(0); STS(0); __syncthreads();
    for (int kt = 0; kt < 49; ++kt) {
        const int cur = kt & 1;
        if (kt < 48) LDG(kt + 1);
#pragma unroll
        for (int k = 0; k < 16; k++) {
            u64 av[4];
#pragma unroll
            for (int p = 0; p < 4; p++) av[p] = *(const u64*)&As[cur][k][ty * 2 + p * 32];
#pragma unroll
            for (int jj = 0; jj < 7; jj++) {
                u64 bd = Bs[cur][k][tx + jj * 16];
#pragma unroll
                for (int p = 0; p < 4; p++) ffma2(acc[p][jj], av[p], bd);
            }
        }
        if (kt < 48) STS(cur ^ 1);
        __syncthreads();
    }

#pragma unroll
    for (int jj = 0; jj < 7; jj++) {
        const int gc = n0 + tx + jj * 16;        // always < 784
        const float bv = bias[gc];
#pragma unroll
        for (int p = 0; p < 4; p++) {
            float2 v = unpack2(acc[p][jj]);
            const int gr = m0 + ty * 2 + p * 32;
            const float v0 = v.x + bv, v1 = v.y + bv;
            if (OUT_SEL == 0) {
                outp[(size_t)gr * Cn + gc] = v0;
                outp[(size_t)(gr + 1) * Cn + gc] = v1;
            } else {
                float* dst = (OUT_SEL == 1) ? g_q : (OUT_SEL == 2) ? g_k : g_v;
                const int h = gc / Dn, dd = gc % Dn;
                const int b0_ = gr / Tn, n0_ = gr % Tn;
                dst[((size_t)(b0_ * Hn + h) * Tn + n0_) * Dn + dd] = v0;
                const int b1_ = (gr + 1) / Tn, n1_ = (gr + 1) % Tn;
                dst[((size_t)(b1_ * Hn + h) * Tn + n1_) * Dn + dd] = v1;
            }
        }
    }
}

// ---------------------------------------------------------------------------
// Logits: L[p][m] = sum_t Q[p][t]*K[m][t]/14 + sum_t C[p][t]*Q[t][m]
// CTA 128(p) x 112(m), BK=16 over t. Single smem buffer + register prefetch.
// ---------------------------------------------------------------------------
__global__ void __launch_bounds__(256, 2) logits_kernel()
{
    const int bh = blockIdx.z;
    const int h  = bh & 3;
    const int p0 = blockIdx.y * 128;
    const int m0 = blockIdx.x * 112;
    const float* __restrict__ Q  = g_q  + (size_t)bh * SQn;
    const float* __restrict__ Kp = g_k  + (size_t)bh * SQn;
    const float* __restrict__ CP = g_cp + (size_t)h  * SQn;

    __shared__ __align__(16) float Aq[16][132];   // [t][p]
    __shared__ __align__(16) float Ac[16][132];   // [t][p]
    __shared__ __align__(16) u64  Bkd[16][114];   // [t][m] dup, pre-scaled 1/14
    __shared__ __align__(16) u64  Bqd[16][114];   // [t][m] dup (Q^T side)

    const int tid = threadIdx.x;
    const int ty = tid >> 4, tx = tid & 15;
    const int lr = tid >> 2, lc4 = (tid & 3) * 4;
    const int cc = tid >> 4;            // t-row for Bq loads
    const int m4 = (tid & 15) * 4;
    const float invs = 1.0f / 14.0f;

    u64 acc[4][7];
#pragma unroll
    for (int i = 0; i < 4; i++)
#pragma unroll
        for (int j = 0; j < 7; j++) acc[i][j] = 0ull;

    float4 qa0, qa1, ca0, ca1, kb0, kb1, qb0, qb1;
    auto LDG = [&](int kt) {
        const int t0 = kt * 16;
        const bool kv = (t0 + lc4) < Tn;      // float4-granular (196 % 4 == 0)
        const bool pa0 = kv && (p0 + lr) < Tn;
        const bool pa1 = kv && (p0 + lr + 64) < Tn;
        qa0 = pa0 ? *(const float4*)(Q  + (p0 + lr) * Dn + t0 + lc4) : f4zero();
        qa1 = pa1 ? *(const float4*)(Q  + (p0 + lr + 64) * Dn + t0 + lc4) : f4zero();
        ca0 = pa0 ? *(const float4*)(CP + (p0 + lr) * Dn + t0 + lc4) : f4zero();
        ca1 = pa1 ? *(const float4*)(CP + (p0 + lr + 64) * Dn + t0 + lc4) : f4zero();
        kb0 = (kv && (m0 + lr) < Tn) ? *(const float4*)(Kp + (m0 + lr) * Dn + t0 + lc4) : f4zero();
        kb1 = (kv && lr < 48 && (m0 + 64 + lr) < Tn)
                  ? *(const float4*)(Kp + (m0 + 64 + lr) * Dn + t0 + lc4) : f4zero();
        const bool tq = (t0 + cc) < Tn;
        qb0 = tq ? *(const float4*)(Q + (t0 + cc) * Dn + m0 + m4) : f4zero();
        qb1 = (tq && m4 < 48 && (m0 + 64 + m4) < Tn)
                  ? *(const float4*)(Q + (t0 + cc) * Dn + m0 + 64 + m4) : f4zero();
    };
    auto STS = [&]() {
        Aq[lc4 + 0][lr] = qa0.x; Aq[lc4 + 1][lr] = qa0.y; Aq[lc4 + 2][lr] = qa0.z; Aq[lc4 + 3][lr] = qa0.w;
        Aq[lc4 + 0][lr + 64] = qa1.x; Aq[lc4 + 1][lr + 64] = qa1.y; Aq[lc4 + 2][lr + 64] = qa1.z; Aq[lc4 + 3][lr + 64] = qa1.w;
        Ac[lc4 + 0][lr] = ca0.x; Ac[lc4 + 1][lr] = ca0.y; Ac[lc4 + 2][lr] = ca0.z; Ac[lc4 + 3][lr] = ca0.w;
        Ac[lc4 + 0][lr + 64] = ca1.x; Ac[lc4 + 1][lr + 64] = ca1.y; Ac[lc4 + 2][lr + 64] = ca1.z; Ac[lc4 + 3][lr + 64] = ca1.w;
        Bkd[lc4 + 0][lr] = dup2(kb0.x * invs); Bkd[lc4 + 1][lr] = dup2(kb0.y * invs);
        Bkd[lc4 + 2][lr] = dup2(kb0.z * invs); Bkd[lc4 + 3][lr] = dup2(kb0.w * invs);
        if (lr < 48) {
            Bkd[lc4 + 0][64 + lr] = dup2(kb1.x * invs); Bkd[lc4 + 1][64 + lr] = dup2(kb1.y * invs);
            Bkd[lc4 + 2][64 + lr] = dup2(kb1.z * invs); Bkd[lc4 + 3][64 + lr] = dup2(kb1.w * invs);
        }
        Bqd[cc][m4 + 0] = dup2(qb0.x); Bqd[cc][m4 + 1] = dup2(qb0.y);
        Bqd[cc][m4 + 2] = dup2(qb0.z); Bqd[cc][m4 + 3] = dup2(qb0.w);
        if (m4 < 48) {
            Bqd[cc][64 + m4 + 0] = dup2(qb1.x); Bqd[cc][64 + m4 + 1] = dup2(qb1.y);
            Bqd[cc][64 + m4 + 2] = dup2(qb1.z); Bqd[cc][64 + m4 + 3] = dup2(qb1.w);
        }
    };

    LDG(0);
    for (int kt = 0; kt < 13; ++kt) {
        __syncthreads();
        STS();
        __syncthreads();
        if (kt < 12) LDG(kt + 1);
#pragma unroll
        for (int k = 0; k < 16; k++) {
            u64 aqv[4], acv[4];
#pragma unroll
            for (int p = 0; p < 4; p++) {
                aqv[p] = *(const u64*)&Aq[k][ty * 2 + p * 32];
                acv[p] = *(const u64*)&Ac[k][ty * 2 + p * 32];
            }
#pragma unroll
            for (int jj = 0; jj < 7; jj++) {
                u64 bkd = Bkd[k][tx + jj * 16];
                u64 bqd = Bqd[k][tx + jj * 16];
#pragma unroll
                for (int p = 0; p < 4; p++) {
                    ffma2(acc[p][jj], aqv[p], bkd);
                    ffma2(acc[p][jj], acv[p], bqd);
                }
            }
        }
    }

    float* __restrict__ L = g_l + (size_t)bh * SQn;
#pragma unroll
    for (int jj = 0; jj < 7; jj++) {
        const int m = m0 + tx + jj * 16;
        if (m >= Tn) continue;
#pragma unroll
        for (int p = 0; p < 4; p++) {
            float2 v = unpack2(acc[p][jj]);
            const int pr = p0 + ty * 2 + p * 32;
            if (pr < Tn)     L[pr * Tn + m] = v.x;
            if (pr + 1 < Tn) L[(pr + 1) * Tn + m] = v.y;
        }
    }
}

// ---------------------------------------------------------------------------
__global__ void __launch_bounds__(256) softmax_kernel()
{
    int gw = (blockIdx.x * blockDim.x + threadIdx.x) >> 5;
    int lane = threadIdx.x & 31;
    if (gw >= BHn * Tn) return;
    float* __restrict__ row = g_l + (size_t)gw * Tn;

    float v[7];
    float mx = -3.0e38f;
#pragma unroll
    for (int w = 0; w < 7; w++) {
        int idx = lane + w * 32;
        v[w] = (idx < Tn) ? row[idx] : -3.0e38f;
        mx = fmaxf(mx, v[w]);
    }
#pragma unroll
    for (int o = 16; o > 0; o >>= 1) mx = fmaxf(mx, __shfl_xor_sync(0xffffffffu, mx, o));

    float s = 0.f;
#pragma unroll
    for (int w = 0; w < 7; w++) {
        int idx = lane + w * 32;
        float e = (idx < Tn) ? __expf(v[w] - mx) : 0.f;
        v[w] = e; s += e;
    }
#pragma unroll
    for (int o = 16; o > 0; o >>= 1) s += __shfl_xor_sync(0xffffffffu, s, o);

    float inv = 1.0f / s;
#pragma unroll
    for (int w = 0; w < 7; w++) {
        int idx = lane + w * 32;
        if (idx < Tn) row[idx] = v[w] * inv;
    }
}

// ---------------------------------------------------------------------------
// O[bh][p][dd] = sum_m A[bh][p][m] * V[bh][m][dd]  -> g_o (b,n,c) layout.
// CTA 128(p) x 112(d), BK=16 over m, double-buffered, dup'd V operand.
// ---------------------------------------------------------------------------
__global__ void __launch_bounds__(256, 2) av_kernel()
{
    const int bh = blockIdx.z;
    const int b = bh >> 2, h = bh & 3;
    const int p0 = blockIdx.y * 128;
    const int d0 = blockIdx.x * 112;
    const float* __restrict__ Att = g_l + (size_t)bh * SQn;
    const float* __restrict__ V   = g_v + (size_t)bh * SQn;

    __shared__ __align__(16) float As[2][16][132];   // [buf][m][p]
    __shared__ __align__(16) u64  Bsd[2][16][114];   // [buf][m][d] dup

    const int tid = threadIdx.x;
    const int ty = tid >> 4, tx = tid & 15;
    const int lr = tid >> 2, lc4 = (tid & 3) * 4;
    const int cc = tid >> 4;
    const int m4 = (tid & 15) * 4;

    u64 acc[4][7];
#pragma unroll
    for (int i = 0; i < 4; i++)
#pragma unroll
        for (int j = 0; j < 7; j++) acc[i][j] = 0ull;

    float4 a0, a1, b0, b1;
    auto LDG = [&](int kt) {
        const int t0 = kt * 16;
        const bool kv = (t0 + lc4) < Tn;
        a0 = (kv && (p0 + lr) < Tn)      ? *(const float4*)(Att + (p0 + lr) * Tn + t0 + lc4) : f4zero();
        a1 = (kv && (p0 + lr + 64) < Tn) ? *(const float4*)(Att + (p0 + lr + 64) * Tn + t0 + lc4) : f4zero();
        const bool tq = (t0 + cc) < Tn;
        b0 = tq ? *(const float4*)(V + (t0 + cc) * Dn + d0 + m4) : f4zero();
        b1 = (tq && m4 < 48 && (d0 + 64 + m4) < Dn)
                 ? *(const float4*)(V + (t0 + cc) * Dn + d0 + 64 + m4) : f4zero();
    };
    auto STS = [&](int bf) {
        As[bf][lc4 + 0][lr] = a0.x; As[bf][lc4 + 1][lr] = a0.y;
        As[bf][lc4 + 2][lr] = a0.z; As[bf][lc4 + 3][lr] = a0.w;
        As[bf][lc4 + 0][lr + 64] = a1.x; As[bf][lc4 + 1][lr + 64] = a1.y;
        As[bf][lc4 + 2][lr + 64] = a1.z; As[bf][lc4 + 3][lr + 64] = a1.w;
        Bsd[bf][cc][m4 + 0] = dup2(b0.x); Bsd[bf][cc][m4 + 1] = dup2(b0.y);
        Bsd[bf][cc][m4 + 2] = dup2(b0.z); Bsd[bf][cc][m4 + 3] = dup2(b0.w);
        if (m4 < 48) {
            Bsd[bf][cc][64 + m4 + 0] = dup2(b1.x); Bsd[bf][cc][64 + m4 + 1] = dup2(b1.y);
            Bsd[bf][cc][64 + m4 + 2] = dup2(b1.z); Bsd[bf][cc][64 + m4 + 3] = dup2(b1.w);
        }
    };

    LDG(0); STS(0); __syncthreads();
    for (int kt = 0; kt < 13; ++kt) {
        const int cur = kt & 1;
        if (kt < 12) LDG(kt + 1);
#pragma unroll
        for (int k = 0; k < 16; k++) {
            u64 av[4];
#pragma unroll
            for (int p = 0; p < 4; p++) av[p] = *(const u64*)&As[cur][k][ty * 2 + p * 32];
#pragma unroll
            for (int jj = 0; jj < 7; jj++) {
                u64 bd = Bsd[cur][k][tx + jj * 16];
#pragma unroll
                for (int p = 0; p < 4; p++) ffma2(acc[p][jj], av[p], bd);
            }
        }
        if (kt < 12) STS(cur ^ 1);
        __syncthreads();
    }

#pragma unroll
    for (int jj = 0; jj < 7; jj++) {
        const int dd = d0 + tx + jj * 16;
        if (dd >= Dn) continue;
#pragma unroll
        for (int p = 0; p < 4; p++) {
            float2 v = unpack2(acc[p][jj]);
            const int pr = p0 + ty * 2 + p * 32;
            if (pr < Tn)
                g_o[(size_t)(b * Tn + pr) * Cn + h * Dn + dd] = v.x;
            if (pr + 1 < Tn)
                g_o[(size_t)(b * Tn + pr + 1) * Cn + h * Dn + dd] = v.y;
        }
    }
}

// ---------------------------------------------------------------------------
extern "C" void kernel_launch(void* const* d_in, const int* in_sizes, int n_in,
                              void* d_out, int out_size)
{
    const float* x    = (const float*)d_in[0];
    const float* Wq   = (const float*)d_in[1];
    const float* bq   = (const float*)d_in[2];
    const float* Wk   = (const float*)d_in[3];
    const float* bk   = (const float*)d_in[4];
    const float* Wv   = (const float*)d_in[5];
    const float* bv   = (const float*)d_in[6];
    const float* Wo   = (const float*)d_in[7];
    const float* bo   = (const float*)d_in[8];
    const float* relh = (const float*)d_in[9];
    const float* relw = (const float*)d_in[10];
    float* out = (float*)d_out;

    build_cp_kernel<<<(Hn * SQn + 255) / 256, 256>>>(relh, relw);

    dim3 pg(7, 392);   // 7 col tiles of 112 (exact 784), 392 row tiles of 128
    proj_kernel<1><<<pg, 256>>>(x, Wq, bq, nullptr);
    proj_kernel<2><<<pg, 256>>>(x, Wk, bk, nullptr);
    proj_kernel<3><<<pg, 256>>>(x, Wv, bv, nullptr);

    logits_kernel<<<dim3(2, 2, BHn), 256>>>();
    softmax_kernel<<<(BHn * Tn) / 8, 256>>>();
    av_kernel<<<dim3(2, 2, BHn), 256>>>();

    proj_kernel<0><<<pg, 256>>>(nullptr, Wo, bo, out);
}

// round 15
// speedup vs baseline: 1.6148x; 1.6148x over previous
#include <cuda_runtime.h>
#include <cuda_bf16.h>

// ---------------------------------------------------------------------------
// MHSA with (bug-faithful) RPE.
//   Projections: bf16-split folded into K (A_ext=[hi|hi|lo], W_ext=[hi|lo|hi])
//   via ldmatrix + mma.sync.m16n8k16 (bf16 -> fp32). No tcgen05 (ptxas target
//   is compute_103, arch-specific instrs unavailable).
//   Attention (logits/softmax/AV): fp32 FFMA2 (proven R9 kernels).
// ---------------------------------------------------------------------------

typedef unsigned long long u64;
typedef unsigned int u32;

constexpr int Bn = 256;
constexpr int Tn = 196;
constexpr int Cn = 784;
constexpr int Hn = 4;
constexpr int Dn = 196;
constexpr int HGTn = 14;
constexpr int WIDn = 14;
constexpr int BHn = Bn * Hn;     // 1024
constexpr int SQn = Tn * Dn;     // 38416
constexpr int Rows = Bn * Tn;    // 50176
constexpr int KExt = 2400;       // 3 blocks of 800 (784 + 16 zero pad)

__device__ float g_q[(size_t)BHn * SQn];
__device__ float g_k[(size_t)BHn * SQn];
__device__ float g_v[(size_t)BHn * SQn];
__device__ float g_l[(size_t)BHn * SQn];
__device__ float g_o[(size_t)Rows * Cn];
__device__ float g_cp[(size_t)Hn * SQn];

__device__ __nv_bfloat16 g_aext[(size_t)Rows * KExt];      // 241 MB
__device__ __nv_bfloat16 g_wext[4][(size_t)Cn * KExt];     // 4 x 3.8 MB

static __device__ __forceinline__ float4 f4zero() { return make_float4(0.f, 0.f, 0.f, 0.f); }

static __device__ __forceinline__ u64 dup2(float v) {
    u64 r; asm("mov.b64 %0, {%1,%1};" : "=l"(r) : "f"(v)); return r;
}
static __device__ __forceinline__ void ffma2(u64& d, u64 a, u64 b) {
    asm("fma.rn.f32x2 %0, %1, %2, %3;" : "=l"(d) : "l"(a), "l"(b), "l"(d));
}
static __device__ __forceinline__ float2 unpack2(u64 p) {
    float2 f; asm("mov.b64 {%0,%1}, %2;" : "=f"(f.x), "=f"(f.y) : "l"(p)); return f;
}

static __device__ __forceinline__ u32 s2u(const void* p) {
    u32 a;
    asm("{ .reg .u64 t; cvta.to.shared.u64 t, %1; cvt.u32.u64 %0, t; }" : "=r"(a) : "l"(p));
    return a;
}
static __device__ __forceinline__ void ldsm4(u32& r0, u32& r1, u32& r2, u32& r3, u32 a) {
    asm volatile("ldmatrix.sync.aligned.m8n8.x4.shared.b16 {%0,%1,%2,%3}, [%4];"
                 : "=r"(r0), "=r"(r1), "=r"(r2), "=r"(r3) : "r"(a));
}
static __device__ __forceinline__ void ldsm2(u32& r0, u32& r1, u32 a) {
    asm volatile("ldmatrix.sync.aligned.m8n8.x2.shared.b16 {%0,%1}, [%2];"
                 : "=r"(r0), "=r"(r1) : "r"(a));
}
static __device__ __forceinline__ void mma16816(float* c, const u32* a, const u32* b) {
    asm volatile(
        "mma.sync.aligned.m16n8k16.row.col.f32.bf16.bf16.f32 "
        "{%0,%1,%2,%3}, {%4,%5,%6,%7}, {%8,%9}, {%0,%1,%2,%3};"
        : "+f"(c[0]), "+f"(c[1]), "+f"(c[2]), "+f"(c[3])
        : "r"(a[0]), "r"(a[1]), "r"(a[2]), "r"(a[3]), "r"(b[0]), "r"(b[1]));
}

// ---------------------------------------------------------------------------
__global__ void build_cp_kernel(const float* __restrict__ rel_h,
                                const float* __restrict__ rel_w)
{
    int idx = blockIdx.x * blockDim.x + threadIdx.x;
    if (idx >= Hn * SQn) return;
    int t = idx % Dn;
    int p = (idx / Dn) % Tn;
    int h = idx / (Dn * Tn);
    g_cp[idx] = rel_h[(h * Dn + t) * HGTn + (p / WIDn)]
              + rel_w[(h * Dn + t) * WIDn + (p % WIDn)];
}

// ---------------------------------------------------------------------------
// Build split-extended bf16 matrices.
//   A (DSTW<0):  [hi | hi | lo]   blocks of 800 (784 data + 16 zeros)
//   W (DSTW>=0): [hi | lo | hi]
// SRC: 0 = read from srcp, 1 = read from g_o.
// ---------------------------------------------------------------------------
template <int SRC, int DSTW>
__global__ void conv_ext_kernel(const float* __restrict__ srcp, int total)
{
    int idx = blockIdx.x * blockDim.x + threadIdx.x;
    if (idx >= total) return;                     // total = rows * 600
    int row = idx / 600;
    int c4 = (idx - row * 600) * 4;
    int region = c4 / 800;
    int scol = c4 - region * 800;
    const bool use_lo = (region == ((DSTW >= 0) ? 1 : 2));

    const float* __restrict__ src = (SRC == 1) ? g_o : srcp;
    float4 v = (scol < Cn) ? *(const float4*)(src + (size_t)row * Cn + scol) : f4zero();

    float vv[4] = {v.x, v.y, v.z, v.w};
    __nv_bfloat16 o[4];
#pragma unroll
    for (int i = 0; i < 4; i++) {
        __nv_bfloat16 h = __float2bfloat16_rn(vv[i]);
        o[i] = use_lo ? __float2bfloat16_rn(vv[i] - __bfloat162float(h)) : h;
    }
    __nv_bfloat16* dst = (DSTW >= 0) ? g_wext[DSTW] : g_aext;
    __nv_bfloat162* d2 = (__nv_bfloat162*)(dst + (size_t)row * KExt + c4);
    d2[0] = __nv_bfloat162(o[0], o[1]);
    d2[1] = __nv_bfloat162(o[2], o[3]);
}

// ---------------------------------------------------------------------------
// bf16 tensor-core projection:
//   out[M=50176, N=784] = A_ext[M, 2400] * W_ext[N-slice, 2400]^T + bias
// CTA 128(M) x 112(N), BK=32, 8 warps (4Mx2N), warp tile 32x56 (2x7 frags).
// Smem row pitch 80B -> conflict-free ldmatrix without swizzle.
// OUT_SEL: 0 -> row-major outp; 1/2/3 -> scatter g_q/g_k/g_v ((b,h) layout).
// ---------------------------------------------------------------------------
template <int OUT_SEL>
__global__ void __launch_bounds__(256, 2) tproj_kernel(const float* __restrict__ bias,
                                                       float* __restrict__ outp)
{
    constexpr int WI = (OUT_SEL == 0) ? 3 : OUT_SEL - 1;
    __shared__ __align__(16) __nv_bfloat16 As[2][128][40];   // 2 x 10240 B
    __shared__ __align__(16) __nv_bfloat16 Bs[2][112][40];   // 2 x  8960 B

    const int tid = threadIdx.x;
    const int lane = tid & 31;
    const int warp = tid >> 5;
    const int wm = warp & 3;        // 0..3 -> M offset 32*wm
    const int wn = warp >> 2;       // 0..1 -> N offset 56*wn
    const int m0 = blockIdx.y * 128;
    const int n0 = blockIdx.x * 112;

    const __nv_bfloat16* __restrict__ A = g_aext;
    const __nv_bfloat16* __restrict__ W = g_wext[WI];

    // ---- global load mapping: 8-half chunks ----
    const int gr_ = tid >> 2;            // 0..63
    const int gch = (tid & 3) * 8;       // 0,8,16,24 halves
    const __nv_bfloat16* ap0 = A + (size_t)(m0 + gr_) * KExt + gch;
    const __nv_bfloat16* ap1 = ap0 + (size_t)64 * KExt;
    const __nv_bfloat16* bp0 = W + (size_t)(n0 + gr_) * KExt + gch;
    const __nv_bfloat16* bp1 = W + (size_t)(n0 + 64 + gr_) * KExt + gch;
    const bool bp1v = (tid < 192);       // rows 64..111 only

    uint4 ra0, ra1, rb0, rb1;
    auto LDG = [&](int k0) {
        ra0 = *(const uint4*)(ap0 + k0);
        ra1 = *(const uint4*)(ap1 + k0);
        rb0 = *(const uint4*)(bp0 + k0);
        if (bp1v) rb1 = *(const uint4*)(bp1 + k0);
    };
    auto STS = [&](int bf) {
        *(uint4*)&As[bf][gr_][gch] = ra0;
        *(uint4*)&As[bf][64 + gr_][gch] = ra1;
        *(uint4*)&Bs[bf][gr_][gch] = rb0;
        if (bp1v) *(uint4*)&Bs[bf][64 + gr_][gch] = rb1;
    };

    // ---- ldmatrix lane offsets (bytes within a buffer) ----
    const int l15 = lane & 15, lh = lane >> 4;
    const u32 asb = s2u(&As[0][0][0]);
    const u32 bsb = s2u(&Bs[0][0][0]);
    u32 aoff[2], boff4[3];
#pragma unroll
    for (int i = 0; i < 2; i++)
        aoff[i] = (u32)((wm * 32 + i * 16 + l15) * 80 + lh * 16);
#pragma unroll
    for (int j = 0; j < 3; j++)
        boff4[j] = (u32)((wn * 56 + j * 16 + l15) * 80 + lh * 16);
    const u32 boff2 = (u32)((wn * 56 + 48 + (lane & 7)) * 80 + ((lane >> 3) & 1) * 16);

    float c[2][7][4];
#pragma unroll
    for (int i = 0; i < 2; i++)
#pragma unroll
        for (int j = 0; j < 7; j++)
#pragma unroll
            for (int q = 0; q < 4; q++) c[i][j][q] = 0.f;

    LDG(0); STS(0); __syncthreads();

    for (int kt = 0; kt < 75; ++kt) {
        const int cur = kt & 1;
        if (kt < 74) LDG((kt + 1) * 32);
        const u32 ab = asb + cur * 10240;
        const u32 bb = bsb + cur * 8960;
#pragma unroll
        for (int kk = 0; kk < 2; kk++) {
            const u32 ko = kk * 32;      // 16 halves
            u32 af[2][4], bfr[7][2], t0, t1, t2, t3;
            ldsm4(af[0][0], af[0][1], af[0][2], af[0][3], ab + aoff[0] + ko);
            ldsm4(af[1][0], af[1][1], af[1][2], af[1][3], ab + aoff[1] + ko);
#pragma unroll
            for (int j = 0; j < 3; j++) {
                ldsm4(t0, t1, t2, t3, bb + boff4[j] + ko);
                bfr[2 * j][0] = t0; bfr[2 * j][1] = t2;
                bfr[2 * j + 1][0] = t1; bfr[2 * j + 1][1] = t3;
            }
            ldsm2(bfr[6][0], bfr[6][1], bb + boff2 + ko);
#pragma unroll
            for (int i = 0; i < 2; i++)
#pragma unroll
                for (int j = 0; j < 7; j++) mma16816(c[i][j], af[i], bfr[j]);
        }
        if (kt < 74) STS(cur ^ 1);
        __syncthreads();
    }

    // ---- epilogue: fragment-direct stores, bias add (no predication) ----
    const int g = lane >> 2, tl = lane & 3;
    auto ST = [&](int gr, int gc, float val) {
        if (OUT_SEL == 0) {
            outp[(size_t)gr * Cn + gc] = val;
        } else {
            float* dst = (OUT_SEL == 1) ? g_q : (OUT_SEL == 2) ? g_k : g_v;
            int h = gc / Dn, dd = gc - h * Dn;
            int b = gr / Tn, n = gr - b * Tn;
            dst[((size_t)(b * Hn + h) * Tn + n) * Dn + dd] = val;
        }
    };
#pragma unroll
    for (int i = 0; i < 2; i++) {
        const int gm = m0 + wm * 32 + i * 16 + g;
#pragma unroll
        for (int j = 0; j < 7; j++) {
            const int gn = n0 + wn * 56 + j * 8 + tl * 2;
            const float bv0 = bias[gn], bv1 = bias[gn + 1];
            ST(gm,     gn,     c[i][j][0] + bv0);
            ST(gm,     gn + 1, c[i][j][1] + bv1);
            ST(gm + 8, gn,     c[i][j][2] + bv0);
            ST(gm + 8, gn + 1, c[i][j][3] + bv1);
        }
    }
}

// ---------------------------------------------------------------------------
// Logits: L[p][m] = sum_t Q[p][t]*K[m][t]/14 + sum_t C[p][t]*Q[t][m]
// CTA 128(p) x 112(m), BK=16 over t. (FFMA2, proven)
// ---------------------------------------------------------------------------
__global__ void __launch_bounds__(256, 2) logits_kernel()
{
    const int bh = blockIdx.z;
    const int h  = bh & 3;
    const int p0 = blockIdx.y * 128;
    const int m0 = blockIdx.x * 112;
    const float* __restrict__ Q  = g_q  + (size_t)bh * SQn;
    const float* __restrict__ Kq = g_k  + (size_t)bh * SQn;
    const float* __restrict__ CP = g_cp + (size_t)h  * SQn;

    __shared__ __align__(16) float Aq[16][132];
    __shared__ __align__(16) float Ac[16][132];
    __shared__ __align__(16) u64  Bkd[16][114];
    __shared__ __align__(16) u64  Bqd[16][114];

    const int tid = threadIdx.x;
    const int ty = tid >> 4, tx = tid & 15;
    const int lr = tid >> 2, lc4 = (tid & 3) * 4;
    const int cc = tid >> 4;
    const int m4 = (tid & 15) * 4;
    const float invs = 1.0f / 14.0f;

    u64 acc[4][7];
#pragma unroll
    for (int i = 0; i < 4; i++)
#pragma unroll
        for (int j = 0; j < 7; j++) acc[i][j] = 0ull;

    float4 qa0, qa1, ca0, ca1, kb0, kb1, qb0, qb1;
    auto LDG = [&](int kt) {
        const int t0 = kt * 16;
        const bool kv = (t0 + lc4) < Tn;
        const bool pa0 = kv && (p0 + lr) < Tn;
        const bool pa1 = kv && (p0 + lr + 64) < Tn;
        qa0 = pa0 ? *(const float4*)(Q  + (p0 + lr) * Dn + t0 + lc4) : f4zero();
        qa1 = pa1 ? *(const float4*)(Q  + (p0 + lr + 64) * Dn + t0 + lc4) : f4zero();
        ca0 = pa0 ? *(const float4*)(CP + (p0 + lr) * Dn + t0 + lc4) : f4zero();
        ca1 = pa1 ? *(const float4*)(CP + (p0 + lr + 64) * Dn + t0 + lc4) : f4zero();
        kb0 = (kv && (m0 + lr) < Tn) ? *(const float4*)(Kq + (m0 + lr) * Dn + t0 + lc4) : f4zero();
        kb1 = (kv && lr < 48 && (m0 + 64 + lr) < Tn)
                  ? *(const float4*)(Kq + (m0 + 64 + lr) * Dn + t0 + lc4) : f4zero();
        const bool tq = (t0 + cc) < Tn;
        qb0 = tq ? *(const float4*)(Q + (t0 + cc) * Dn + m0 + m4) : f4zero();
        qb1 = (tq && m4 < 48 && (m0 + 64 + m4) < Tn)
                  ? *(const float4*)(Q + (t0 + cc) * Dn + m0 + 64 + m4) : f4zero();
    };
    auto STS = [&]() {
        Aq[lc4 + 0][lr] = qa0.x; Aq[lc4 + 1][lr] = qa0.y; Aq[lc4 + 2][lr] = qa0.z; Aq[lc4 + 3][lr] = qa0.w;
        Aq[lc4 + 0][lr + 64] = qa1.x; Aq[lc4 + 1][lr + 64] = qa1.y; Aq[lc4 + 2][lr + 64] = qa1.z; Aq[lc4 + 3][lr + 64] = qa1.w;
        Ac[lc4 + 0][lr] = ca0.x; Ac[lc4 + 1][lr] = ca0.y; Ac[lc4 + 2][lr] = ca0.z; Ac[lc4 + 3][lr] = ca0.w;
        Ac[lc4 + 0][lr + 64] = ca1.x; Ac[lc4 + 1][lr + 64] = ca1.y; Ac[lc4 + 2][lr + 64] = ca1.z; Ac[lc4 + 3][lr + 64] = ca1.w;
        Bkd[lc4 + 0][lr] = dup2(kb0.x * invs); Bkd[lc4 + 1][lr] = dup2(kb0.y * invs);
        Bkd[lc4 + 2][lr] = dup2(kb0.z * invs); Bkd[lc4 + 3][lr] = dup2(kb0.w * invs);
        if (lr < 48) {
            Bkd[lc4 + 0][64 + lr] = dup2(kb1.x * invs); Bkd[lc4 + 1][64 + lr] = dup2(kb1.y * invs);
            Bkd[lc4 + 2][64 + lr] = dup2(kb1.z * invs); Bkd[lc4 + 3][64 + lr] = dup2(kb1.w * invs);
        }
        Bqd[cc][m4 + 0] = dup2(qb0.x); Bqd[cc][m4 + 1] = dup2(qb0.y);
        Bqd[cc][m4 + 2] = dup2(qb0.z); Bqd[cc][m4 + 3] = dup2(qb0.w);
        if (m4 < 48) {
            Bqd[cc][64 + m4 + 0] = dup2(qb1.x); Bqd[cc][64 + m4 + 1] = dup2(qb1.y);
            Bqd[cc][64 + m4 + 2] = dup2(qb1.z); Bqd[cc][64 + m4 + 3] = dup2(qb1.w);
        }
    };

    LDG(0);
    for (int kt = 0; kt < 13; ++kt) {
        __syncthreads();
        STS();
        __syncthreads();
        if (kt < 12) LDG(kt + 1);
#pragma unroll
        for (int k = 0; k < 16; k++) {
            u64 aqv[4], acv[4];
#pragma unroll
            for (int p = 0; p < 4; p++) {
                aqv[p] = *(const u64*)&Aq[k][ty * 2 + p * 32];
                acv[p] = *(const u64*)&Ac[k][ty * 2 + p * 32];
            }
#pragma unroll
            for (int jj = 0; jj < 7; jj++) {
                u64 bkd = Bkd[k][tx + jj * 16];
                u64 bqd = Bqd[k][tx + jj * 16];
#pragma unroll
                for (int p = 0; p < 4; p++) {
                    ffma2(acc[p][jj], aqv[p], bkd);
                    ffma2(acc[p][jj], acv[p], bqd);
                }
            }
        }
    }

    float* __restrict__ L = g_l + (size_t)bh * SQn;
#pragma unroll
    for (int jj = 0; jj < 7; jj++) {
        const int m = m0 + tx + jj * 16;
        if (m >= Tn) continue;
#pragma unroll
        for (int p = 0; p < 4; p++) {
            float2 v = unpack2(acc[p][jj]);
            const int pr = p0 + ty * 2 + p * 32;
            if (pr < Tn)     L[pr * Tn + m] = v.x;
            if (pr + 1 < Tn) L[(pr + 1) * Tn + m] = v.y;
        }
    }
}

// ---------------------------------------------------------------------------
__global__ void __launch_bounds__(256) softmax_kernel()
{
    int gw = (blockIdx.x * blockDim.x + threadIdx.x) >> 5;
    int lane = threadIdx.x & 31;
    if (gw >= BHn * Tn) return;
    float* __restrict__ row = g_l + (size_t)gw * Tn;

    float v[7];
    float mx = -3.0e38f;
#pragma unroll
    for (int w = 0; w < 7; w++) {
        int idx = lane + w * 32;
        v[w] = (idx < Tn) ? row[idx] : -3.0e38f;
        mx = fmaxf(mx, v[w]);
    }
#pragma unroll
    for (int o = 16; o > 0; o >>= 1) mx = fmaxf(mx, __shfl_xor_sync(0xffffffffu, mx, o));

    float s = 0.f;
#pragma unroll
    for (int w = 0; w < 7; w++) {
        int idx = lane + w * 32;
        float e = (idx < Tn) ? __expf(v[w] - mx) : 0.f;
        v[w] = e; s += e;
    }
#pragma unroll
    for (int o = 16; o > 0; o >>= 1) s += __shfl_xor_sync(0xffffffffu, s, o);

    float inv = 1.0f / s;
#pragma unroll
    for (int w = 0; w < 7; w++) {
        int idx = lane + w * 32;
        if (idx < Tn) row[idx] = v[w] * inv;
    }
}

// ---------------------------------------------------------------------------
// O[bh][p][dd] = sum_m A[bh][p][m] * V[bh][m][dd]  -> g_o (b,n,c) layout.
// (FFMA2 double-buffered, proven)
// ---------------------------------------------------------------------------
__global__ void __launch_bounds__(256, 2) av_kernel()
{
    const int bh = blockIdx.z;
    const int b = bh >> 2, h = bh & 3;
    const int p0 = blockIdx.y * 128;
    const int d0 = blockIdx.x * 112;
    const float* __restrict__ Att = g_l + (size_t)bh * SQn;
    const float* __restrict__ V   = g_v + (size_t)bh * SQn;

    __shared__ __align__(16) float As[2][16][132];
    __shared__ __align__(16) u64  Bsd[2][16][114];

    const int tid = threadIdx.x;
    const int ty = tid >> 4, tx = tid & 15;
    const int lr = tid >> 2, lc4 = (tid & 3) * 4;
    const int cc = tid >> 4;
    const int m4 = (tid & 15) * 4;

    u64 acc[4][7];
#pragma unroll
    for (int i = 0; i < 4; i++)
#pragma unroll
        for (int j = 0; j < 7; j++) acc[i][j] = 0ull;

    float4 a0, a1, b0, b1;
    auto LDG = [&](int kt) {
        const int t0 = kt * 16;
        const bool kv = (t0 + lc4) < Tn;
        a0 = (kv && (p0 + lr) < Tn)      ? *(const float4*)(Att + (p0 + lr) * Tn + t0 + lc4) : f4zero();
        a1 = (kv && (p0 + lr + 64) < Tn) ? *(const float4*)(Att + (p0 + lr + 64) * Tn + t0 + lc4) : f4zero();
        const bool tq = (t0 + cc) < Tn;
        b0 = tq ? *(const float4*)(V + (t0 + cc) * Dn + d0 + m4) : f4zero();
        b1 = (tq && m4 < 48 && (d0 + 64 + m4) < Dn)
                 ? *(const float4*)(V + (t0 + cc) * Dn + d0 + 64 + m4) : f4zero();
    };
    auto STS = [&](int bf) {
        As[bf][lc4 + 0][lr] = a0.x; As[bf][lc4 + 1][lr] = a0.y;
        As[bf][lc4 + 2][lr] = a0.z; As[bf][lc4 + 3][lr] = a0.w;
        As[bf][lc4 + 0][lr + 64] = a1.x; As[bf][lc4 + 1][lr + 64] = a1.y;
        As[bf][lc4 + 2][lr + 64] = a1.z; As[bf][lc4 + 3][lr + 64] = a1.w;
        Bsd[bf][cc][m4 + 0] = dup2(b0.x); Bsd[bf][cc][m4 + 1] = dup2(b0.y);
        Bsd[bf][cc][m4 + 2] = dup2(b0.z); Bsd[bf][cc][m4 + 3] = dup2(b0.w);
        if (m4 < 48) {
            Bsd[bf][cc][64 + m4 + 0] = dup2(b1.x); Bsd[bf][cc][64 + m4 + 1] = dup2(b1.y);
            Bsd[bf][cc][64 + m4 + 2] = dup2(b1.z); Bsd[bf][cc][64 + m4 + 3] = dup2(b1.w);
        }
    };

    LDG(0); STS(0); __syncthreads();
    for (int kt = 0; kt < 13; ++kt) {
        const int cur = kt & 1;
        if (kt < 12) LDG(kt + 1);
#pragma unroll
        for (int k = 0; k < 16; k++) {
            u64 av[4];
#pragma unroll
            for (int p = 0; p < 4; p++) av[p] = *(const u64*)&As[cur][k][ty * 2 + p * 32];
#pragma unroll
            for (int jj = 0; jj < 7; jj++) {
                u64 bd = Bsd[cur][k][tx + jj * 16];
#pragma unroll
                for (int p = 0; p < 4; p++) ffma2(acc[p][jj], av[p], bd);
            }
        }
        if (kt < 12) STS(cur ^ 1);
        __syncthreads();
    }

#pragma unroll
    for (int jj = 0; jj < 7; jj++) {
        const int dd = d0 + tx + jj * 16;
        if (dd >= Dn) continue;
#pragma unroll
        for (int p = 0; p < 4; p++) {
            float2 v = unpack2(acc[p][jj]);
            const int pr = p0 + ty * 2 + p * 32;
            if (pr < Tn)
                g_o[(size_t)(b * Tn + pr) * Cn + h * Dn + dd] = v.x;
            if (pr + 1 < Tn)
                g_o[(size_t)(b * Tn + pr + 1) * Cn + h * Dn + dd] = v.y;
        }
    }
}

// ---------------------------------------------------------------------------
extern "C" void kernel_launch(void* const* d_in, const int* in_sizes, int n_in,
                              void* d_out, int out_size)
{
    const float* x    = (const float*)d_in[0];
    const float* Wq   = (const float*)d_in[1];
    const float* bq   = (const float*)d_in[2];
    const float* Wk   = (const float*)d_in[3];
    const float* bk   = (const float*)d_in[4];
    const float* Wv   = (const float*)d_in[5];
    const float* bv   = (const float*)d_in[6];
    const float* Wo   = (const float*)d_in[7];
    const float* bo   = (const float*)d_in[8];
    const float* relh = (const float*)d_in[9];
    const float* relw = (const float*)d_in[10];
    float* out = (float*)d_out;

    build_cp_kernel<<<(Hn * SQn + 255) / 256, 256>>>(relh, relw);

    const int xtot = Rows * 600;
    const int wtot = Cn * 600;
    conv_ext_kernel<0, -1><<<(xtot + 255) / 256, 256>>>(x, xtot);
    conv_ext_kernel<0, 0><<<(wtot + 255) / 256, 256>>>(Wq, wtot);
    conv_ext_kernel<0, 1><<<(wtot + 255) / 256, 256>>>(Wk, wtot);
    conv_ext_kernel<0, 2><<<(wtot + 255) / 256, 256>>>(Wv, wtot);
    conv_ext_kernel<0, 3><<<(wtot + 255) / 256, 256>>>(Wo, wtot);

    dim3 pg(7, 392);     // 7 N-tiles of 112 (exact), 392 M-tiles of 128
    tproj_kernel<1><<<pg, 256>>>(bq, nullptr);
    tproj_kernel<2><<<pg, 256>>>(bk, nullptr);
    tproj_kernel<3><<<pg, 256>>>(bv, nullptr);

    logits_kernel<<<dim3(2, 2, BHn), 256>>>();
    softmax_kernel<<<(BHn * Tn) / 8, 256>>>();
    av_kernel<<<dim3(2, 2, BHn), 256>>>();

    conv_ext_kernel<1, -1><<<(xtot + 255) / 256, 256>>>(nullptr, xtot);
    tproj_kernel<0><<<pg, 256>>>(bo, out);
}

// round 17
// speedup vs baseline: 1.6409x; 1.0161x over previous
#include <cuda_runtime.h>
#include <cuda_bf16.h>

// ---------------------------------------------------------------------------
// MHSA with (bug-faithful) RPE.
//   Projections: bf16-split folded into K (A_ext=[hi|hi|lo], W_ext=[hi|lo|hi])
//   via ldmatrix + mma.sync.m16n8k16, 4-stage cp.async pipeline, QKV fused.
//   Attention (logits/softmax/AV): fp32 FFMA2 (proven kernels).
// ---------------------------------------------------------------------------

typedef unsigned long long u64;
typedef unsigned int u32;

constexpr int Bn = 256;
constexpr int Tn = 196;
constexpr int Cn = 784;
constexpr int Hn = 4;
constexpr int Dn = 196;
constexpr int HGTn = 14;
constexpr int WIDn = 14;
constexpr int BHn = Bn * Hn;     // 1024
constexpr int SQn = Tn * Dn;     // 38416
constexpr int Rows = Bn * Tn;    // 50176
constexpr int KExt = 2400;       // 3 blocks of 800 (784 + 16 zero pad)

constexpr int STAGES = 4;
constexpr int STAGE_BYTES = 19200;          // A 128*80 + B 112*80
constexpr int DYN_SMEM = STAGES * STAGE_BYTES;   // 76800

__device__ float g_q[(size_t)BHn * SQn];
__device__ float g_k[(size_t)BHn * SQn];
__device__ float g_v[(size_t)BHn * SQn];
__device__ float g_l[(size_t)BHn * SQn];
__device__ float g_o[(size_t)Rows * Cn];
__device__ float g_cp[(size_t)Hn * SQn];

__device__ __nv_bfloat16 g_aext[(size_t)Rows * KExt];      // 241 MB
__device__ __nv_bfloat16 g_wext[4][(size_t)Cn * KExt];     // 4 x 3.8 MB

static __device__ __forceinline__ float4 f4zero() { return make_float4(0.f, 0.f, 0.f, 0.f); }

static __device__ __forceinline__ u64 dup2(float v) {
    u64 r; asm("mov.b64 %0, {%1,%1};" : "=l"(r) : "f"(v)); return r;
}
static __device__ __forceinline__ void ffma2(u64& d, u64 a, u64 b) {
    asm("fma.rn.f32x2 %0, %1, %2, %3;" : "=l"(d) : "l"(a), "l"(b), "l"(d));
}
static __device__ __forceinline__ float2 unpack2(u64 p) {
    float2 f; asm("mov.b64 {%0,%1}, %2;" : "=f"(f.x), "=f"(f.y) : "l"(p)); return f;
}

static __device__ __forceinline__ u32 s2u(const void* p) {
    u32 a;
    asm("{ .reg .u64 t; cvta.to.shared.u64 t, %1; cvt.u32.u64 %0, t; }" : "=r"(a) : "l"(p));
    return a;
}
static __device__ __forceinline__ void ldsm4(u32& r0, u32& r1, u32& r2, u32& r3, u32 a) {
    asm volatile("ldmatrix.sync.aligned.m8n8.x4.shared.b16 {%0,%1,%2,%3}, [%4];"
                 : "=r"(r0), "=r"(r1), "=r"(r2), "=r"(r3) : "r"(a));
}
static __device__ __forceinline__ void ldsm2(u32& r0, u32& r1, u32 a) {
    asm volatile("ldmatrix.sync.aligned.m8n8.x2.shared.b16 {%0,%1}, [%2];"
                 : "=r"(r0), "=r"(r1) : "r"(a));
}
static __device__ __forceinline__ void mma16816(float* c, const u32* a, const u32* b) {
    asm volatile(
        "mma.sync.aligned.m16n8k16.row.col.f32.bf16.bf16.f32 "
        "{%0,%1,%2,%3}, {%4,%5,%6,%7}, {%8,%9}, {%0,%1,%2,%3};"
        : "+f"(c[0]), "+f"(c[1]), "+f"(c[2]), "+f"(c[3])
        : "r"(a[0]), "r"(a[1]), "r"(a[2]), "r"(a[3]), "r"(b[0]), "r"(b[1]));
}
static __device__ __forceinline__ void cpa16(u32 dst, const void* src) {
    asm volatile("cp.async.cg.shared.global [%0], [%1], 16;" :: "r"(dst), "l"(src) : "memory");
}
static __device__ __forceinline__ void cpa_commit() {
    asm volatile("cp.async.commit_group;" ::: "memory");
}

// ---------------------------------------------------------------------------
__global__ void build_cp_kernel(const float* __restrict__ rel_h,
                                const float* __restrict__ rel_w)
{
    int idx = blockIdx.x * blockDim.x + threadIdx.x;
    if (idx >= Hn * SQn) return;
    int t = idx % Dn;
    int p = (idx / Dn) % Tn;
    int h = idx / (Dn * Tn);
    g_cp[idx] = rel_h[(h * Dn + t) * HGTn + (p / WIDn)]
              + rel_w[(h * Dn + t) * WIDn + (p % WIDn)];
}

// ---------------------------------------------------------------------------
// Build split-extended bf16 matrices.
//   A (DSTW<0):  [hi | hi | lo]   blocks of 800 (784 data + 16 zeros)
//   W (DSTW>=0): [hi | lo | hi]
// SRC: 0 = read from srcp, 1 = read from g_o.
// ---------------------------------------------------------------------------
template <int SRC, int DSTW>
__global__ void conv_ext_kernel(const float* __restrict__ srcp, int total)
{
    int idx = blockIdx.x * blockDim.x + threadIdx.x;
    if (idx >= total) return;                     // total = rows * 600
    int row = idx / 600;
    int c4 = (idx - row * 600) * 4;
    int region = c4 / 800;
    int scol = c4 - region * 800;
    const bool use_lo = (region == ((DSTW >= 0) ? 1 : 2));

    const float* __restrict__ src = (SRC == 1) ? g_o : srcp;
    float4 v = (scol < Cn) ? *(const float4*)(src + (size_t)row * Cn + scol) : f4zero();

    float vv[4] = {v.x, v.y, v.z, v.w};
    __nv_bfloat16 o[4];
#pragma unroll
    for (int i = 0; i < 4; i++) {
        __nv_bfloat16 h = __float2bfloat16_rn(vv[i]);
        o[i] = use_lo ? __float2bfloat16_rn(vv[i] - __bfloat162float(h)) : h;
    }
    __nv_bfloat16* dst = (DSTW >= 0) ? g_wext[DSTW] : g_aext;
    __nv_bfloat162* d2 = (__nv_bfloat162*)(dst + (size_t)row * KExt + c4);
    d2[0] = __nv_bfloat162(o[0], o[1]);
    d2[1] = __nv_bfloat162(o[2], o[3]);
}

// ---------------------------------------------------------------------------
// bf16 tensor-core projection, 4-stage cp.async pipeline.
//   FUSED=1: one GEMM over N=2352 ([Wq;Wk;Wv]); grid (21, 392); each N-tile
//            lies wholly inside one weight matrix (wsel = bx/7); scatter to
//            g_q/g_k/g_v in (b*H+h, n, d) layout.
//   FUSED=0: Wo projection, grid (7, 392), row-major to outp.
// CTA 128(M) x 112(N), BK=32, 8 warps (4Mx2N), warp tile 32x56 (2x7 frags).
// Smem row pitch 80B -> conflict-free ldmatrix without swizzle.
// ---------------------------------------------------------------------------
template <int FUSED>
__global__ void __launch_bounds__(256, 2) tproj_kernel(const float* __restrict__ b0p,
                                                       const float* __restrict__ b1p,
                                                       const float* __restrict__ b2p,
                                                       float* __restrict__ outp)
{
    extern __shared__ char smem[];
    const u32 sb = s2u(smem);

    const int tid = threadIdx.x;
    const int lane = tid & 31;
    const int warp = tid >> 5;
    const int wm = warp & 3;        // 0..3 -> M offset 32*wm
    const int wn = warp >> 2;       // 0..1 -> N offset 56*wn
    const int m0 = blockIdx.y * 128;
    const int bx = blockIdx.x;
    const int wsel = FUSED ? (bx / 7) : 3;
    const int n0l = FUSED ? (bx % 7) * 112 : bx * 112;   // row within W matrix

    const __nv_bfloat16* __restrict__ A = g_aext;
    const __nv_bfloat16* __restrict__ W = g_wext[wsel];

    // ---- global sources: 16B per thread per row, 4 threads cover 64B (BK=32) ----
    const int gr_ = tid >> 2;             // 0..63
    const int gb  = (tid & 3) * 16;       // byte offset within 64B K-span
    const char* ap0 = (const char*)(A + (size_t)(m0 + gr_) * KExt) + gb;
    const char* ap1 = ap0 + (size_t)64 * KExt * 2;
    const char* bp0 = (const char*)(W + (size_t)(n0l + gr_) * KExt) + gb;
    const char* bp1 = bp0 + (size_t)64 * KExt * 2;
    const bool bp1v = (tid < 192);        // B rows 64..111 only

    // smem dst (per-stage base added later)
    const u32 ad0 = sb + gr_ * 80 + gb;
    const u32 ad1 = ad0 + 64 * 80;
    const u32 bd0 = sb + 10240 + gr_ * 80 + gb;
    const u32 bd1 = bd0 + 64 * 80;

    auto ISSUE = [&](int kt, int st) {
        const int off = kt * 64;
        const u32 s = st * STAGE_BYTES;
        cpa16(ad0 + s, ap0 + off);
        cpa16(ad1 + s, ap1 + off);
        cpa16(bd0 + s, bp0 + off);
        if (bp1v) cpa16(bd1 + s, bp1 + off);
        cpa_commit();
    };

    // ---- ldmatrix lane offsets (relative to stage base) ----
    const int l15 = lane & 15, lh = lane >> 4;
    u32 aoff[2], boff4[3];
#pragma unroll
    for (int i = 0; i < 2; i++)
        aoff[i] = (u32)((wm * 32 + i * 16 + l15) * 80 + lh * 16);
#pragma unroll
    for (int j = 0; j < 3; j++)
        boff4[j] = (u32)(10240 + (wn * 56 + j * 16 + l15) * 80 + lh * 16);
    const u32 boff2 = (u32)(10240 + (wn * 56 + 48 + (lane & 7)) * 80 + ((lane >> 3) & 1) * 16);

    float c[2][7][4];
#pragma unroll
    for (int i = 0; i < 2; i++)
#pragma unroll
        for (int j = 0; j < 7; j++)
#pragma unroll
            for (int q = 0; q < 4; q++) c[i][j][q] = 0.f;

    ISSUE(0, 0); ISSUE(1, 1); ISSUE(2, 2);

    for (int kt = 0; kt < 75; ++kt) {
        if (kt < 73)      asm volatile("cp.async.wait_group 2;" ::: "memory");
        else if (kt == 73) asm volatile("cp.async.wait_group 1;" ::: "memory");
        else               asm volatile("cp.async.wait_group 0;" ::: "memory");
        __syncthreads();
        if (kt <= 71) ISSUE(kt + 3, (kt + 3) & 3);

        const u32 base = sb + (u32)(kt & 3) * STAGE_BYTES;
#pragma unroll
        for (int kk = 0; kk < 2; kk++) {
            const u32 ko = kk * 32;      // 16 halves
            u32 af[2][4], bfr[7][2], t0, t1, t2, t3;
            ldsm4(af[0][0], af[0][1], af[0][2], af[0][3], base + aoff[0] + ko);
            ldsm4(af[1][0], af[1][1], af[1][2], af[1][3], base + aoff[1] + ko);
#pragma unroll
            for (int j = 0; j < 3; j++) {
                ldsm4(t0, t1, t2, t3, base + boff4[j] + ko);
                bfr[2 * j][0] = t0; bfr[2 * j][1] = t2;
                bfr[2 * j + 1][0] = t1; bfr[2 * j + 1][1] = t3;
            }
            ldsm2(bfr[6][0], bfr[6][1], base + boff2 + ko);
#pragma unroll
            for (int i = 0; i < 2; i++)
#pragma unroll
                for (int j = 0; j < 7; j++) mma16816(c[i][j], af[i], bfr[j]);
        }
    }

    // ---- epilogue: fragment-direct stores, bias add (no predication) ----
    const float* bias = FUSED ? ((wsel == 0) ? b0p : (wsel == 1) ? b1p : b2p) : b0p;
    float* dstq = (wsel == 0) ? g_q : (wsel == 1) ? g_k : g_v;
    const int g = lane >> 2, tl = lane & 3;
#pragma unroll
    for (int i = 0; i < 2; i++) {
        const int gm = m0 + wm * 32 + i * 16 + g;
        const int b_ = gm / Tn, n_ = gm - b_ * Tn;
        const int b1_ = (gm + 8) / Tn, n1_ = (gm + 8) - b1_ * Tn;
#pragma unroll
        for (int j = 0; j < 7; j++) {
            const int lc = n0l + wn * 56 + j * 8 + tl * 2;     // col within 784
            const float bv0 = bias[lc], bv1 = bias[lc + 1];
            if (FUSED) {
                const int h = lc / Dn, dd = lc - h * Dn;
                float* d0 = dstq + ((size_t)(b_ * Hn + h) * Tn + n_) * Dn + dd;
                float* d1 = dstq + ((size_t)(b1_ * Hn + h) * Tn + n1_) * Dn + dd;
                d0[0] = c[i][j][0] + bv0; d0[1] = c[i][j][1] + bv1;
                d1[0] = c[i][j][2] + bv0; d1[1] = c[i][j][3] + bv1;
            } else {
                outp[(size_t)gm * Cn + lc]       = c[i][j][0] + bv0;
                outp[(size_t)gm * Cn + lc + 1]   = c[i][j][1] + bv1;
                outp[(size_t)(gm + 8) * Cn + lc]     = c[i][j][2] + bv0;
                outp[(size_t)(gm + 8) * Cn + lc + 1] = c[i][j][3] + bv1;
            }
        }
    }
}

// ---------------------------------------------------------------------------
// Logits: L[p][m] = sum_t Q[p][t]*K[m][t]/14 + sum_t C[p][t]*Q[t][m]
// CTA 128(p) x 112(m), BK=16 over t. (FFMA2, proven)
// ---------------------------------------------------------------------------
__global__ void __launch_bounds__(256, 2) logits_kernel()
{
    const int bh = blockIdx.z;
    const int h  = bh & 3;
    const int p0 = blockIdx.y * 128;
    const int m0 = blockIdx.x * 112;
    const float* __restrict__ Q  = g_q  + (size_t)bh * SQn;
    const float* __restrict__ Kq = g_k  + (size_t)bh * SQn;
    const float* __restrict__ CP = g_cp + (size_t)h  * SQn;

    __shared__ __align__(16) float Aq[16][132];
    __shared__ __align__(16) float Ac[16][132];
    __shared__ __align__(16) u64  Bkd[16][114];
    __shared__ __align__(16) u64  Bqd[16][114];

    const int tid = threadIdx.x;
    const int ty = tid >> 4, tx = tid & 15;
    const int lr = tid >> 2, lc4 = (tid & 3) * 4;
    const int cc = tid >> 4;
    const int m4 = (tid & 15) * 4;
    const float invs = 1.0f / 14.0f;

    u64 acc[4][7];
#pragma unroll
    for (int i = 0; i < 4; i++)
#pragma unroll
        for (int j = 0; j < 7; j++) acc[i][j] = 0ull;

    float4 qa0, qa1, ca0, ca1, kb0, kb1, qb0, qb1;
    auto LDG = [&](int kt) {
        const int t0 = kt * 16;
        const bool kv = (t0 + lc4) < Tn;
        const bool pa0 = kv && (p0 + lr) < Tn;
        const bool pa1 = kv && (p0 + lr + 64) < Tn;
        qa0 = pa0 ? *(const float4*)(Q  + (p0 + lr) * Dn + t0 + lc4) : f4zero();
        qa1 = pa1 ? *(const float4*)(Q  + (p0 + lr + 64) * Dn + t0 + lc4) : f4zero();
        ca0 = pa0 ? *(const float4*)(CP + (p0 + lr) * Dn + t0 + lc4) : f4zero();
        ca1 = pa1 ? *(const float4*)(CP + (p0 + lr + 64) * Dn + t0 + lc4) : f4zero();
        kb0 = (kv && (m0 + lr) < Tn) ? *(const float4*)(Kq + (m0 + lr) * Dn + t0 + lc4) : f4zero();
        kb1 = (kv && lr < 48 && (m0 + 64 + lr) < Tn)
                  ? *(const float4*)(Kq + (m0 + 64 + lr) * Dn + t0 + lc4) : f4zero();
        const bool tq = (t0 + cc) < Tn;
        qb0 = tq ? *(const float4*)(Q + (t0 + cc) * Dn + m0 + m4) : f4zero();
        qb1 = (tq && m4 < 48 && (m0 + 64 + m4) < Tn)
                  ? *(const float4*)(Q + (t0 + cc) * Dn + m0 + 64 + m4) : f4zero();
    };
    auto STS = [&]() {
        Aq[lc4 + 0][lr] = qa0.x; Aq[lc4 + 1][lr] = qa0.y; Aq[lc4 + 2][lr] = qa0.z; Aq[lc4 + 3][lr] = qa0.w;
        Aq[lc4 + 0][lr + 64] = qa1.x; Aq[lc4 + 1][lr + 64] = qa1.y; Aq[lc4 + 2][lr + 64] = qa1.z; Aq[lc4 + 3][lr + 64] = qa1.w;
        Ac[lc4 + 0][lr] = ca0.x; Ac[lc4 + 1][lr] = ca0.y; Ac[lc4 + 2][lr] = ca0.z; Ac[lc4 + 3][lr] = ca0.w;
        Ac[lc4 + 0][lr + 64] = ca1.x; Ac[lc4 + 1][lr + 64] = ca1.y; Ac[lc4 + 2][lr + 64] = ca1.z; Ac[lc4 + 3][lr + 64] = ca1.w;
        Bkd[lc4 + 0][lr] = dup2(kb0.x * invs); Bkd[lc4 + 1][lr] = dup2(kb0.y * invs);
        Bkd[lc4 + 2][lr] = dup2(kb0.z * invs); Bkd[lc4 + 3][lr] = dup2(kb0.w * invs);
        if (lr < 48) {
            Bkd[lc4 + 0][64 + lr] = dup2(kb1.x * invs); Bkd[lc4 + 1][64 + lr] = dup2(kb1.y * invs);
            Bkd[lc4 + 2][64 + lr] = dup2(kb1.z * invs); Bkd[lc4 + 3][64 + lr] = dup2(kb1.w * invs);
        }
        Bqd[cc][m4 + 0] = dup2(qb0.x); Bqd[cc][m4 + 1] = dup2(qb0.y);
        Bqd[cc][m4 + 2] = dup2(qb0.z); Bqd[cc][m4 + 3] = dup2(qb0.w);
        if (m4 < 48) {
            Bqd[cc][64 + m4 + 0] = dup2(qb1.x); Bqd[cc][64 + m4 + 1] = dup2(qb1.y);
            Bqd[cc][64 + m4 + 2] = dup2(qb1.z); Bqd[cc][64 + m4 + 3] = dup2(qb1.w);
        }
    };

    LDG(0);
    for (int kt = 0; kt < 13; ++kt) {
        __syncthreads();
        STS();
        __syncthreads();
        if (kt < 12) LDG(kt + 1);
#pragma unroll
        for (int k = 0; k < 16; k++) {
            u64 aqv[4], acv[4];
#pragma unroll
            for (int p = 0; p < 4; p++) {
                aqv[p] = *(const u64*)&Aq[k][ty * 2 + p * 32];
                acv[p] = *(const u64*)&Ac[k][ty * 2 + p * 32];
            }
#pragma unroll
            for (int jj = 0; jj < 7; jj++) {
                u64 bkd = Bkd[k][tx + jj * 16];
                u64 bqd = Bqd[k][tx + jj * 16];
#pragma unroll
                for (int p = 0; p < 4; p++) {
                    ffma2(acc[p][jj], aqv[p], bkd);
                    ffma2(acc[p][jj], acv[p], bqd);
                }
            }
        }
    }

    float* __restrict__ L = g_l + (size_t)bh * SQn;
#pragma unroll
    for (int jj = 0; jj < 7; jj++) {
        const int m = m0 + tx + jj * 16;
        if (m >= Tn) continue;
#pragma unroll
        for (int p = 0; p < 4; p++) {
            float2 v = unpack2(acc[p][jj]);
            const int pr = p0 + ty * 2 + p * 32;
            if (pr < Tn)     L[pr * Tn + m] = v.x;
            if (pr + 1 < Tn) L[(pr + 1) * Tn + m] = v.y;
        }
    }
}

// ---------------------------------------------------------------------------
__global__ void __launch_bounds__(256) softmax_kernel()
{
    int gw = (blockIdx.x * blockDim.x + threadIdx.x) >> 5;
    int lane = threadIdx.x & 31;
    if (gw >= BHn * Tn) return;
    float* __restrict__ row = g_l + (size_t)gw * Tn;

    float v[7];
    float mx = -3.0e38f;
#pragma unroll
    for (int w = 0; w < 7; w++) {
        int idx = lane + w * 32;
        v[w] = (idx < Tn) ? row[idx] : -3.0e38f;
        mx = fmaxf(mx, v[w]);
    }
#pragma unroll
    for (int o = 16; o > 0; o >>= 1) mx = fmaxf(mx, __shfl_xor_sync(0xffffffffu, mx, o));

    float s = 0.f;
#pragma unroll
    for (int w = 0; w < 7; w++) {
        int idx = lane + w * 32;
        float e = (idx < Tn) ? __expf(v[w] - mx) : 0.f;
        v[w] = e; s += e;
    }
#pragma unroll
    for (int o = 16; o > 0; o >>= 1) s += __shfl_xor_sync(0xffffffffu, s, o);

    float inv = 1.0f / s;
#pragma unroll
    for (int w = 0; w < 7; w++) {
        int idx = lane + w * 32;
        if (idx < Tn) row[idx] = v[w] * inv;
    }
}

// ---------------------------------------------------------------------------
// O[bh][p][dd] = sum_m A[bh][p][m] * V[bh][m][dd]  -> g_o (b,n,c) layout.
// (FFMA2 double-buffered, proven)
// ---------------------------------------------------------------------------
__global__ void __launch_bounds__(256, 2) av_kernel()
{
    const int bh = blockIdx.z;
    const int b = bh >> 2, h = bh & 3;
    const int p0 = blockIdx.y * 128;
    const int d0 = blockIdx.x * 112;
    const float* __restrict__ Att = g_l + (size_t)bh * SQn;
    const float* __restrict__ V   = g_v + (size_t)bh * SQn;

    __shared__ __align__(16) float As[2][16][132];
    __shared__ __align__(16) u64  Bsd[2][16][114];

    const int tid = threadIdx.x;
    const int ty = tid >> 4, tx = tid & 15;
    const int lr = tid >> 2, lc4 = (tid & 3) * 4;
    const int cc = tid >> 4;
    const int m4 = (tid & 15) * 4;

    u64 acc[4][7];
#pragma unroll
    for (int i = 0; i < 4; i++)
#pragma unroll
        for (int j = 0; j < 7; j++) acc[i][j] = 0ull;

    float4 a0, a1, b0, b1;
    auto LDG = [&](int kt) {
        const int t0 = kt * 16;
        const bool kv = (t0 + lc4) < Tn;
        a0 = (kv && (p0 + lr) < Tn)      ? *(const float4*)(Att + (p0 + lr) * Tn + t0 + lc4) : f4zero();
        a1 = (kv && (p0 + lr + 64) < Tn) ? *(const float4*)(Att + (p0 + lr + 64) * Tn + t0 + lc4) : f4zero();
        const bool tq = (t0 + cc) < Tn;
        b0 = tq ? *(const float4*)(V + (t0 + cc) * Dn + d0 + m4) : f4zero();
        b1 = (tq && m4 < 48 && (d0 + 64 + m4) < Dn)
                 ? *(const float4*)(V + (t0 + cc) * Dn + d0 + 64 + m4) : f4zero();
    };
    auto STS = [&](int bf) {
        As[bf][lc4 + 0][lr] = a0.x; As[bf][lc4 + 1][lr] = a0.y;
        As[bf][lc4 + 2][lr] = a0.z; As[bf][lc4 + 3][lr] = a0.w;
        As[bf][lc4 + 0][lr + 64] = a1.x; As[bf][lc4 + 1][lr + 64] = a1.y;
        As[bf][lc4 + 2][lr + 64] = a1.z; As[bf][lc4 + 3][lr + 64] = a1.w;
        Bsd[bf][cc][m4 + 0] = dup2(b0.x); Bsd[bf][cc][m4 + 1] = dup2(b0.y);
        Bsd[bf][cc][m4 + 2] = dup2(b0.z); Bsd[bf][cc][m4 + 3] = dup2(b0.w);
        if (m4 < 48) {
            Bsd[bf][cc][64 + m4 + 0] = dup2(b1.x); Bsd[bf][cc][64 + m4 + 1] = dup2(b1.y);
            Bsd[bf][cc][64 + m4 + 2] = dup2(b1.z); Bsd[bf][cc][64 + m4 + 3] = dup2(b1.w);
        }
    };

    LDG(0); STS(0); __syncthreads();
    for (int kt = 0; kt < 13; ++kt) {
        const int cur = kt & 1;
        if (kt < 12) LDG(kt + 1);
#pragma unroll
        for (int k = 0; k < 16; k++) {
            u64 av[4];
#pragma unroll
            for (int p = 0; p < 4; p++) av[p] = *(const u64*)&As[cur][k][ty * 2 + p * 32];
#pragma unroll
            for (int jj = 0; jj < 7; jj++) {
                u64 bd = Bsd[cur][k][tx + jj * 16];
#pragma unroll
                for (int p = 0; p < 4; p++) ffma2(acc[p][jj], av[p], bd);
            }
        }
        if (kt < 12) STS(cur ^ 1);
        __syncthreads();
    }

#pragma unroll
    for (int jj = 0; jj < 7; jj++) {
        const int dd = d0 + tx + jj * 16;
        if (dd >= Dn) continue;
#pragma unroll
        for (int p = 0; p < 4; p++) {
            float2 v = unpack2(acc[p][jj]);
            const int pr = p0 + ty * 2 + p * 32;
            if (pr < Tn)
                g_o[(size_t)(b * Tn + pr) * Cn + h * Dn + dd] = v.x;
            if (pr + 1 < Tn)
                g_o[(size_t)(b * Tn + pr + 1) * Cn + h * Dn + dd] = v.y;
        }
    }
}

// ---------------------------------------------------------------------------
extern "C" void kernel_launch(void* const* d_in, const int* in_sizes, int n_in,
                              void* d_out, int out_size)
{
    const float* x    = (const float*)d_in[0];
    const float* Wq   = (const float*)d_in[1];
    const float* bq   = (const float*)d_in[2];
    const float* Wk   = (const float*)d_in[3];
    const float* bk   = (const float*)d_in[4];
    const float* Wv   = (const float*)d_in[5];
    const float* bv   = (const float*)d_in[6];
    const float* Wo   = (const float*)d_in[7];
    const float* bo   = (const float*)d_in[8];
    const float* relh = (const float*)d_in[9];
    const float* relw = (const float*)d_in[10];
    float* out = (float*)d_out;

    cudaFuncSetAttribute(tproj_kernel<1>, cudaFuncAttributeMaxDynamicSharedMemorySize, DYN_SMEM);
    cudaFuncSetAttribute(tproj_kernel<0>, cudaFuncAttributeMaxDynamicSharedMemorySize, DYN_SMEM);

    build_cp_kernel<<<(Hn * SQn + 255) / 256, 256>>>(relh, relw);

    const int xtot = Rows * 600;
    const int wtot = Cn * 600;
    conv_ext_kernel<0, -1><<<(xtot + 255) / 256, 256>>>(x, xtot);
    conv_ext_kernel<0, 0><<<(wtot + 255) / 256, 256>>>(Wq, wtot);
    conv_ext_kernel<0, 1><<<(wtot + 255) / 256, 256>>>(Wk, wtot);
    conv_ext_kernel<0, 2><<<(wtot + 255) / 256, 256>>>(Wv, wtot);
    conv_ext_kernel<0, 3><<<(wtot + 255) / 256, 256>>>(Wo, wtot);

    // Fused QKV projection: N = 2352 -> 21 tiles of 112
    tproj_kernel<1><<<dim3(21, 392), 256, DYN_SMEM>>>(bq, bk, bv, nullptr);

    logits_kernel<<<dim3(2, 2, BHn), 256>>>();
    softmax_kernel<<<(BHn * Tn) / 8, 256>>>();
    av_kernel<<<dim3(2, 2, BHn), 256>>>();

    conv_ext_kernel<1, -1><<<(xtot + 255) / 256, 256>>>(nullptr, xtot);
    tproj_kernel<0><<<dim3(7, 392), 256, DYN_SMEM>>>(bo, nullptr, nullptr, out);
}